// round 12
// baseline (speedup 1.0000x reference)
#include <cuda_runtime.h>
#include <cuda_bf16.h>
#include <cuda_fp16.h>
#include <math.h>
#include <cstdint>

#define BB 128
#define TT 512
#define II 512
#define HH 512
#define H3 1536
#define KK 512
#define NCTA 128

// ---------------- scratch (device globals: allocation-free) ----------------
__device__ float g_xlin[(size_t)BB * TT * H3];            // [B,T,3H]
__device__ __half g_hb16[2][BB * HH];                     // h fp16 ping-pong
__device__ __nv_bfloat16 g_xhi[(size_t)BB * TT * II];     // x hi (bf16)
__device__ __nv_bfloat16 g_xlo[(size_t)BB * TT * II];     // x lo
__device__ __nv_bfloat16 g_wxhi[H3 * II];                 // Wx hi
__device__ __nv_bfloat16 g_wxlo[H3 * II];                 // Wx lo
__device__ __half g_whh16[H3 * KK];                       // Wh fp16, gate-permuted
__device__ int g_bar_count;

// ================= PTX helpers (baseline ISA only: sm_80+) =================
#define CP_ASYNC16(dst, src) \
    asm volatile("cp.async.cg.shared.global [%0], [%1], 16;" \
                 :: "r"(dst), "l"(src) : "memory")
#define CP_COMMIT() asm volatile("cp.async.commit_group;" ::: "memory")
template <int N>
__device__ __forceinline__ void cp_wait() {
    asm volatile("cp.async.wait_group %0;" :: "n"(N) : "memory");
}

__device__ __forceinline__ uint32_t smem_to_u32(const void* p) {
    uint32_t a;
    asm("{ .reg .u64 t; cvta.to.shared.u64 t, %1; cvt.u32.u64 %0, t; }"
        : "=r"(a) : "l"(p));
    return a;
}

__device__ __forceinline__ void ldmatrix_x4(uint32_t& r0, uint32_t& r1,
                                            uint32_t& r2, uint32_t& r3,
                                            uint32_t addr) {
    asm volatile("ldmatrix.sync.aligned.m8n8.x4.shared.b16 {%0,%1,%2,%3}, [%4];"
                 : "=r"(r0), "=r"(r1), "=r"(r2), "=r"(r3) : "r"(addr));
}

__device__ __forceinline__ void ldmatrix_x2(uint32_t& r0, uint32_t& r1,
                                            uint32_t addr) {
    asm volatile("ldmatrix.sync.aligned.m8n8.x2.shared.b16 {%0,%1}, [%2];"
                 : "=r"(r0), "=r"(r1) : "r"(addr));
}

__device__ __forceinline__ void mma_bf16(float* c, const uint32_t* a,
                                         const uint32_t* b) {
    asm volatile(
        "mma.sync.aligned.m16n8k16.row.col.f32.bf16.bf16.f32 "
        "{%0,%1,%2,%3}, {%4,%5,%6,%7}, {%8,%9}, {%0,%1,%2,%3};"
        : "+f"(c[0]), "+f"(c[1]), "+f"(c[2]), "+f"(c[3])
        : "r"(a[0]), "r"(a[1]), "r"(a[2]), "r"(a[3]), "r"(b[0]), "r"(b[1]));
}

__device__ __forceinline__ void mma_f16(float* c, const uint32_t* a,
                                        const uint32_t* b) {
    asm volatile(
        "mma.sync.aligned.m16n8k16.row.col.f32.f16.f16.f32 "
        "{%0,%1,%2,%3}, {%4,%5,%6,%7}, {%8,%9}, {%0,%1,%2,%3};"
        : "+f"(c[0]), "+f"(c[1]), "+f"(c[2]), "+f"(c[3])
        : "r"(a[0]), "r"(a[1]), "r"(a[2]), "r"(a[3]), "r"(b[0]), "r"(b[1]));
}

// ---------------- small helpers ----------------
__global__ void reset_bar() { g_bar_count = 0; }

__global__ void copy_hfinal(const float* __restrict__ y, float* __restrict__ dst,
                            int n) {
    int i = blockIdx.x * blockDim.x + threadIdx.x;
    if (i >= n) return;
    int b = i >> 9;
    int u = i & 511;
    dst[i] = y[((size_t)b * TT + (TT - 1)) * HH + u];
}

// combined split: x->bf16x2, Wx->bf16x2, Wh->fp16 gate-permuted, h0->fp16
#define NX2 ((size_t)BB * TT * II / 2)
#define NW2 ((size_t)H3 * II / 2)
#define NH2 ((size_t)H3 * KK / 2)
#define NH0 ((size_t)BB * HH / 2)
__global__ void split_all(const float* __restrict__ x,
                          const float* __restrict__ wx,
                          const float* __restrict__ wh,
                          const float* __restrict__ h0,
                          __nv_bfloat16* __restrict__ xhi,
                          __nv_bfloat16* __restrict__ xlo,
                          __nv_bfloat16* __restrict__ wxhi,
                          __nv_bfloat16* __restrict__ wxlo,
                          __half* __restrict__ whh16,
                          __half* __restrict__ hb0) {
    size_t i = (size_t)blockIdx.x * blockDim.x + threadIdx.x;
    if (i < NX2 + NW2) {
        const float* src;
        __nv_bfloat16 *hi, *lo;
        size_t j;
        if (i < NX2) { src = x; hi = xhi; lo = xlo; j = i; }
        else { src = wx; hi = wxhi; lo = wxlo; j = i - NX2; }
        float2 v = ((const float2*)src)[j];
        __nv_bfloat16 h0b = __float2bfloat16(v.x);
        __nv_bfloat16 h1b = __float2bfloat16(v.y);
        ((__nv_bfloat162*)hi)[j] = __nv_bfloat162(h0b, h1b);
        ((__nv_bfloat162*)lo)[j] =
            __nv_bfloat162(__float2bfloat16(v.x - __bfloat162float(h0b)),
                           __float2bfloat16(v.y - __bfloat162float(h1b)));
    } else if (i < NX2 + NW2 + NH2) {
        size_t j = i - NX2 - NW2;
        int g = (int)(j >> 8);            // Wh row 0..1535
        int k2 = (int)(j & 255);          // half2 col index
        int gate = g >> 9;
        int u = g & 511;
        int prow = (u >> 3) * 24 + gate * 8 + (u & 7);   // gate-permuted row
        float2 v = ((const float2*)wh)[j];
        ((__half2*)whh16)[(size_t)prow * 256 + k2] =
            __halves2half2(__float2half_rn(v.x), __float2half_rn(v.y));
    } else if (i < NX2 + NW2 + NH2 + NH0) {
        size_t j = i - NX2 - NW2 - NH2;
        float2 v = ((const float2*)h0)[j];
        ((__half2*)hb0)[j] = __halves2half2(__float2half_rn(v.x),
                                            __float2half_rn(v.y));
    }
}

// ---------------- Phase 1: bf16-split GEMM, 3-stage cp.async pipeline -----
#define SA 40
#define A_T (128 * SA * 2)
#define B_T (64 * SA * 2)
#define STG_B (2 * A_T + 2 * B_T)           // 30720 per stage
#define O_AH 0
#define O_AL A_T
#define O_BH (2 * A_T)
#define O_BL (2 * A_T + B_T)

__global__ void __launch_bounds__(256, 2) gemm_xlin_mma(
    const __nv_bfloat16* __restrict__ Ahi, const __nv_bfloat16* __restrict__ Alo,
    const __nv_bfloat16* __restrict__ Bhi, const __nv_bfloat16* __restrict__ Blo,
    const float* __restrict__ bias, float* __restrict__ C) {
    extern __shared__ char smem[];
    const uint32_t sb = smem_to_u32(smem);

    const int tid = threadIdx.x;
    const int wid = tid >> 5;
    const int lane = tid & 31;
    const int wrow = wid >> 2;
    const int wcol = wid & 3;
    const int n0 = blockIdx.x * 64;
    const int m0 = blockIdx.y * 128;

    const __nv_bfloat16* ga_h = Ahi + (size_t)m0 * KK;
    const __nv_bfloat16* ga_l = Alo + (size_t)m0 * KK;
    const __nv_bfloat16* gb_h = Bhi + (size_t)n0 * KK;
    const __nv_bfloat16* gb_l = Blo + (size_t)n0 * KK;

    const int ra = tid >> 1;
    const int ga2 = (tid & 1) * 2;
    const int rb = tid >> 2;
    const int gb1 = tid & 3;

    auto stage = [&](int kc, int buf) {
        const uint32_t d = sb + buf * STG_B;
        const __nv_bfloat16* sa_h = ga_h + (size_t)ra * KK + kc * 32;
        const __nv_bfloat16* sa_l = ga_l + (size_t)ra * KK + kc * 32;
        CP_ASYNC16(d + O_AH + ra * 80 + ga2 * 16, (const void*)(sa_h + ga2 * 8));
        CP_ASYNC16(d + O_AH + ra * 80 + (ga2 + 1) * 16, (const void*)(sa_h + (ga2 + 1) * 8));
        CP_ASYNC16(d + O_AL + ra * 80 + ga2 * 16, (const void*)(sa_l + ga2 * 8));
        CP_ASYNC16(d + O_AL + ra * 80 + (ga2 + 1) * 16, (const void*)(sa_l + (ga2 + 1) * 8));
        const __nv_bfloat16* sb_h = gb_h + (size_t)rb * KK + kc * 32;
        const __nv_bfloat16* sb_l = gb_l + (size_t)rb * KK + kc * 32;
        CP_ASYNC16(d + O_BH + rb * 80 + gb1 * 16, (const void*)(sb_h + gb1 * 8));
        CP_ASYNC16(d + O_BL + rb * 80 + gb1 * 16, (const void*)(sb_l + gb1 * 8));
        CP_COMMIT();
    };

    float acc[4][2][4];
#pragma unroll
    for (int i = 0; i < 4; i++)
#pragma unroll
        for (int j = 0; j < 2; j++)
#pragma unroll
            for (int q = 0; q < 4; q++) acc[i][j][q] = 0.f;

    const int lrow = lane & 15;
    const int lcol8 = (lane >> 4) * 8;

    const int NCHUNK = KK / 32;             // 16
    stage(0, 0);
    stage(1, 1);

    for (int kc = 0; kc < NCHUNK; kc++) {
        if (kc + 1 < NCHUNK) { cp_wait<1>(); } else { cp_wait<0>(); }
        __syncthreads();                    // chunk kc visible; compute(kc-1) done
        if (kc + 2 < NCHUNK) stage(kc + 2, (kc + 2) % 3);

        const uint32_t bb = sb + (kc % 3) * STG_B;
#pragma unroll
        for (int ks = 0; ks < 2; ks++) {
            const uint32_t coloff = (ks * 16 + lcol8) * 2;
            uint32_t bh[2][2], bl[2][2];
            {
                const uint32_t brow = (wcol * 16 + lrow) * 80;
                uint32_t r0, r1, r2, r3;
                ldmatrix_x4(r0, r1, r2, r3, bb + O_BH + brow + coloff);
                bh[0][0] = r0; bh[1][0] = r1; bh[0][1] = r2; bh[1][1] = r3;
                ldmatrix_x4(r0, r1, r2, r3, bb + O_BL + brow + coloff);
                bl[0][0] = r0; bl[1][0] = r1; bl[0][1] = r2; bl[1][1] = r3;
            }
#pragma unroll
            for (int mt = 0; mt < 4; mt++) {
                const uint32_t arow = (wrow * 64 + mt * 16 + lrow) * 80;
                uint32_t ah[4], al[4];
                ldmatrix_x4(ah[0], ah[1], ah[2], ah[3], bb + O_AH + arow + coloff);
                ldmatrix_x4(al[0], al[1], al[2], al[3], bb + O_AL + arow + coloff);
#pragma unroll
                for (int nt = 0; nt < 2; nt++) {
                    mma_bf16(acc[mt][nt], ah, bh[nt]);
                    mma_bf16(acc[mt][nt], ah, bl[nt]);
                    mma_bf16(acc[mt][nt], al, bh[nt]);
                }
            }
        }
    }

    const int erow = m0 + wrow * 64 + (lane >> 2);
    const int ecol0 = n0 + wcol * 16 + (lane & 3) * 2;
#pragma unroll
    for (int mt = 0; mt < 4; mt++) {
#pragma unroll
        for (int nt = 0; nt < 2; nt++) {
            const int col = ecol0 + nt * 8;
            const float b0 = bias[col], b1 = bias[col + 1];
            const int r0 = erow + mt * 16;
            *(float2*)(C + (size_t)r0 * H3 + col) =
                make_float2(acc[mt][nt][0] + b0, acc[mt][nt][1] + b1);
            *(float2*)(C + (size_t)(r0 + 8) * H3 + col) =
                make_float2(acc[mt][nt][2] + b0, acc[mt][nt][3] + b1);
        }
    }
}

// ---------------- Phase 2: fused recurrence, 512 threads, split barrier ----
// 128 CTAs = 64 unit-groups x 2 batch-halves; CTA tile 64b x 24n x 512k.
// 16 warps: wm = wid&3 (m16-tile), wkg = wid>>2 (k16 % 4 parity group).
// Per-warp chain: 8 do_k (4 per A-chunk). 4-way k-reduce via smem.
// Barrier split arrive/wait: y stores + xlin prefetch overlap the wait skew.
#define RSA 520
#define RSB 520
#define SM_A 0
#define A_SZ (64 * RSA * 2)             // 66560
#define SM_BHI A_SZ
#define B_SZ (24 * RSB * 2)             // 24960
#define SM_RED (SM_BHI + B_SZ)
#define SMT (SM_RED + 3 * 4 * 32 * 13 * 4)  // 111488

__global__ void __launch_bounds__(512, 1) gru_persist_mma(
    const float* __restrict__ xlin,
    const __half* __restrict__ whh16,
    const float* __restrict__ h0,
    __half* __restrict__ hbuf,          // 2 x BB*HH fp16 ping-pong
    float* __restrict__ y) {
    extern __shared__ char smh[];
    const uint32_t sb = smem_to_u32(smh);
    float* red = (float*)(smh + SM_RED);

    const int tid = threadIdx.x;
    const int lane = tid & 31;
    const int wid = tid >> 5;
    const int wm = wid & 3;             // m16-tile 0..3
    const int wkg = wid >> 2;           // k16 parity group 0..3
    const int cta = blockIdx.x;
    const int ug = cta >> 1;            // unit group 0..63
    const int mh = cta & 1;             // batch half
    const int b0 = mh * 64;
    const int lrow = lane & 15;
    const int lcol8 = (lane >> 4) * 8;

    const int gr0 = b0 + wm * 16 + (lane >> 2);
    const int gu0 = ug * 8 + (lane & 3) * 2;

    float hold[2][2];
    if (wkg == 0) {
#pragma unroll
        for (int rh = 0; rh < 2; rh++)
#pragma unroll
            for (int ui = 0; ui < 2; ui++)
                hold[rh][ui] = h0[(gr0 + rh * 8) * HH + gu0 + ui];
    }

    // ---- stage resident permuted Wh tile: rows [ug*24, +24) x 512 k ----
    {
#pragma unroll
        for (int i = 0; i < 3; i++) {
            int c = tid + i * 512;            // 0..1535
            int row = c >> 6;                 // 0..23
            int seg = c & 63;
            CP_ASYNC16(sb + SM_BHI + (row * RSB + seg * 8) * 2,
                       (const void*)(whh16 + (size_t)(ug * 24 + row) * KK + seg * 8));
        }
        CP_COMMIT();
        cp_wait<0>();
    }
    __syncthreads();

    // one k16-step of mma on staged data (k16 = 4j + wkg)
    auto do_k = [&](int j, float acc[3][4]) {
        const int k16 = 4 * j + wkg;
        const uint32_t coloff = (k16 * 16 + lcol8) * 2;
        uint32_t a[4];
        ldmatrix_x4(a[0], a[1], a[2], a[3],
                    sb + SM_A + (wm * 16 + lrow) * (RSA * 2) + coloff);
        uint32_t bh[3][2];
        {
            uint32_t r0, r1, r2, r3;
            ldmatrix_x4(r0, r1, r2, r3, sb + SM_BHI + lrow * (RSB * 2) + coloff);
            bh[0][0] = r0; bh[1][0] = r1; bh[0][1] = r2; bh[1][1] = r3;
            const uint32_t a2 = (16 + (lane & 7)) * (RSB * 2) +
                                (k16 * 16 + ((lane >> 3) & 1) * 8) * 2;
            ldmatrix_x2(bh[2][0], bh[2][1], sb + SM_BHI + a2);
        }
#pragma unroll
        for (int nt = 0; nt < 3; nt++) mma_f16(acc[nt], a, bh[nt]);
    };

    // ---- prologue: prefetch xlin gate operands for t=0 ----
    float px[3][2][2];
    auto prefetch_px = [&](int t) {
        if (wkg == 0) {
            const float* xlb0 = xlin + (size_t)t * H3;
#pragma unroll
            for (int rh = 0; rh < 2; rh++) {
                const float* xl = xlb0 + (size_t)(gr0 + rh * 8) * (TT * H3);
#pragma unroll
                for (int ui = 0; ui < 2; ui++) {
                    px[0][rh][ui] = xl[gu0 + ui];
                    px[1][rh][ui] = xl[gu0 + ui + 512];
                    px[2][rh][ui] = xl[gu0 + ui + 1024];
                }
            }
        }
    };
    prefetch_px(0);

    for (int t = 0; t < TT; t++) {
        // ---- barrier WAIT: h(t-1) stores from all CTAs visible ----
        if (t > 0) {
            if (tid == 0) {
                const int target = NCTA * t;
                while (*((volatile int*)&g_bar_count) < target) { }
                __threadfence();               // acquire
            }
        }
        __syncthreads();

        // ---- stage A = h fp16 [64b x 512k] in 2 chunks (k halves) ----
        const __half* hsrc = hbuf + (size_t)(t & 1) * (BB * HH);
#pragma unroll
        for (int ch = 0; ch < 2; ch++) {
#pragma unroll
            for (int i = 0; i < 4; i++) {
                int c = tid + i * 512;        // 0..2047
                int row = c >> 5;             // 0..63
                int seg = ch * 32 + (c & 31);
                CP_ASYNC16(sb + SM_A + (row * RSA + seg * 8) * 2,
                           (const void*)(hsrc + (size_t)(b0 + row) * HH + seg * 8));
            }
            CP_COMMIT();
        }

        float acc[3][4];
#pragma unroll
        for (int j = 0; j < 3; j++)
#pragma unroll
            for (int q = 0; q < 4; q++) acc[j][q] = 0.f;

        cp_wait<1>();                   // chunk 0 (k16 0..15) ready
        __syncthreads();
#pragma unroll
        for (int j = 0; j < 4; j++) do_k(j, acc);      // k16 {wkg,4+wkg,8+wkg,12+wkg}

        cp_wait<0>();                   // chunk 1 ready
        __syncthreads();
#pragma unroll
        for (int j = 4; j < 8; j++) do_k(j, acc);      // k16 16..31 band

        // ---- 4-way k-parity reduce via smem ----
        if (wkg > 0) {
            float* rp = red + (((wkg - 1) * 4 + wm) * 32 + lane) * 13;
#pragma unroll
            for (int nt = 0; nt < 3; nt++)
#pragma unroll
                for (int q = 0; q < 4; q++) rp[nt * 4 + q] = acc[nt][q];
        }
        __syncthreads();

        // ---- gating (wkg==0): register-local z/r/n triplets ----
        float v[12];
        if (wkg == 0) {
#pragma unroll
            for (int nt = 0; nt < 3; nt++)
#pragma unroll
                for (int q = 0; q < 4; q++) v[nt * 4 + q] = acc[nt][q];
#pragma unroll
            for (int g = 0; g < 3; g++) {
                const float* rp = red + ((g * 4 + wm) * 32 + lane) * 13;
#pragma unroll
                for (int i = 0; i < 12; i++) v[i] += rp[i];
            }
            __half* hdst = hbuf + (size_t)((t + 1) & 1) * (BB * HH);
#pragma unroll
            for (int rh = 0; rh < 2; rh++) {
#pragma unroll
                for (int ui = 0; ui < 2; ui++) {
                    const int q = rh * 2 + ui;
                    float z = 1.f / (1.f + __expf(-(px[0][rh][ui] + v[0 + q])));
                    float r = 1.f / (1.f + __expf(-(px[1][rh][ui] + v[4 + q])));
                    float n = tanhf(px[2][rh][ui] + r * v[8 + q]);
                    float hn = fmaf(z, hold[rh][ui] - n, n);
                    hold[rh][ui] = hn;
                    v[q] = hn;                        // stash hn for y store
                    hdst[(gr0 + rh * 8) * HH + gu0 + ui] = __float2half_rn(hn);
                }
            }
        }
        __syncthreads();                 // all h stores issued block-wide

        // ---- barrier ARRIVE (release h(t) stores) ----
        if (tid == 0) {
            __threadfence();
            atomicAdd(&g_bar_count, 1);
        }

        // ---- overlap window: y stores + next-step xlin prefetch ----
        if (wkg == 0) {
#pragma unroll
            for (int rh = 0; rh < 2; rh++)
#pragma unroll
                for (int ui = 0; ui < 2; ui++)
                    y[((size_t)(gr0 + rh * 8) * TT + t) * HH + gu0 + ui] =
                        v[rh * 2 + ui];
        }
        if (t + 1 < TT) prefetch_px(t + 1);
        // next iteration's wait + syncthreads protects SM_A reuse
    }
}

// ---------------- launch ----------------
extern "C" void kernel_launch(void* const* d_in, const int* in_sizes, int n_in,
                              void* d_out, int out_size) {
    const float* x  = (const float*)d_in[0];  // [B,T,I]
    const float* h0 = (const float*)d_in[1];  // [B,H]
    const float* Wx = (const float*)d_in[2];  // [3H,I]
    const float* bx = (const float*)d_in[3];  // [3H]
    const float* Wh = (const float*)d_in[4];  // [3H,H]
    float* out = (float*)d_out;

    float* xlin;
    __nv_bfloat16 *xhi, *xlo, *wxhi, *wxlo;
    __half *whh16, *hbuf;
    cudaGetSymbolAddress((void**)&xlin, g_xlin);
    cudaGetSymbolAddress((void**)&xhi, g_xhi);
    cudaGetSymbolAddress((void**)&xlo, g_xlo);
    cudaGetSymbolAddress((void**)&wxhi, g_wxhi);
    cudaGetSymbolAddress((void**)&wxlo, g_wxlo);
    cudaGetSymbolAddress((void**)&whh16, g_whh16);
    cudaGetSymbolAddress((void**)&hbuf, g_hb16);

    cudaFuncSetAttribute(gemm_xlin_mma, cudaFuncAttributeMaxDynamicSharedMemorySize,
                         3 * STG_B);
    cudaFuncSetAttribute(gru_persist_mma, cudaFuncAttributeMaxDynamicSharedMemorySize,
                         SMT);

    // launch order: ncu captures index 3 -> the recurrence
    reset_bar<<<1, 1>>>();                                              // 0
    {
        size_t tot = NX2 + NW2 + NH2 + NH0;
        split_all<<<(unsigned)((tot + 255) / 256), 256>>>(              // 1
            x, Wx, Wh, h0, xhi, xlo, wxhi, wxlo, whh16, hbuf);
    }
    gemm_xlin_mma<<<dim3(H3 / 64, (BB * TT) / 128), 256, 3 * STG_B>>>(  // 2
        xhi, xlo, wxhi, wxlo, bx, xlin);
    gru_persist_mma<<<NCTA, 512, SMT>>>(xlin, whh16, h0, hbuf, out);    // 3
    if (out_size >= (int)((size_t)BB * TT * HH + BB * HH)) {
        copy_hfinal<<<(BB * HH + 255) / 256, 256>>>(out, out + (size_t)BB * TT * HH,
                                                    BB * HH);           // 4
    }
}

// round 13
// speedup vs baseline: 1.3199x; 1.3199x over previous
#include <cuda_runtime.h>
#include <cuda_fp16.h>
#include <math.h>
#include <cstdint>

#define BB 128
#define TT 512
#define II 512
#define HH 512
#define H3 1536
#define KK 512
#define NCTA 128

// ---------------- scratch (device globals: allocation-free) ----------------
__device__ __half g_x16[(size_t)BB * TT * II];            // x fp16 [B,T,I]
__device__ __half g_hb16[2][BB * HH];                     // h fp16 ping-pong
__device__ __half g_wxp16[H3 * II];                       // Wx fp16, gate-permuted
__device__ __half g_whp16[H3 * KK];                       // Wh fp16, gate-permuted
__device__ int g_bar_count;

// ================= PTX helpers (baseline ISA only: sm_80+) =================
#define CP_ASYNC16(dst, src) \
    asm volatile("cp.async.cg.shared.global [%0], [%1], 16;" \
                 :: "r"(dst), "l"(src) : "memory")
#define CP_COMMIT() asm volatile("cp.async.commit_group;" ::: "memory")
template <int N>
__device__ __forceinline__ void cp_wait() {
    asm volatile("cp.async.wait_group %0;" :: "n"(N) : "memory");
}

__device__ __forceinline__ uint32_t smem_to_u32(const void* p) {
    uint32_t a;
    asm("{ .reg .u64 t; cvta.to.shared.u64 t, %1; cvt.u32.u64 %0, t; }"
        : "=r"(a) : "l"(p));
    return a;
}

__device__ __forceinline__ void ldmatrix_x4(uint32_t& r0, uint32_t& r1,
                                            uint32_t& r2, uint32_t& r3,
                                            uint32_t addr) {
    asm volatile("ldmatrix.sync.aligned.m8n8.x4.shared.b16 {%0,%1,%2,%3}, [%4];"
                 : "=r"(r0), "=r"(r1), "=r"(r2), "=r"(r3) : "r"(addr));
}

__device__ __forceinline__ void ldmatrix_x2(uint32_t& r0, uint32_t& r1,
                                            uint32_t addr) {
    asm volatile("ldmatrix.sync.aligned.m8n8.x2.shared.b16 {%0,%1}, [%2];"
                 : "=r"(r0), "=r"(r1) : "r"(addr));
}

__device__ __forceinline__ void mma_f16(float* c, const uint32_t* a,
                                        const uint32_t* b) {
    asm volatile(
        "mma.sync.aligned.m16n8k16.row.col.f32.f16.f16.f32 "
        "{%0,%1,%2,%3}, {%4,%5,%6,%7}, {%8,%9}, {%0,%1,%2,%3};"
        : "+f"(c[0]), "+f"(c[1]), "+f"(c[2]), "+f"(c[3])
        : "r"(a[0]), "r"(a[1]), "r"(a[2]), "r"(a[3]), "r"(b[0]), "r"(b[1]));
}

// ---------------- small helpers ----------------
__global__ void reset_bar() { g_bar_count = 0; }

__global__ void copy_hfinal(const float* __restrict__ y, float* __restrict__ dst,
                            int n) {
    int i = blockIdx.x * blockDim.x + threadIdx.x;
    if (i >= n) return;
    int b = i >> 9;
    int u = i & 511;
    dst[i] = y[((size_t)b * TT + (TT - 1)) * HH + u];
}

// combined split: x->fp16, Wx->fp16 gate-permuted, Wh->fp16 gate-permuted,
// h0->fp16. All half2 stores, 2 elems per thread.
#define NX2 ((size_t)BB * TT * II / 2)
#define NW2 ((size_t)H3 * II / 2)
#define NH2 ((size_t)H3 * KK / 2)
#define NH0 ((size_t)BB * HH / 2)
__global__ void split_all(const float* __restrict__ x,
                          const float* __restrict__ wx,
                          const float* __restrict__ wh,
                          const float* __restrict__ h0,
                          __half* __restrict__ x16,
                          __half* __restrict__ wxp,
                          __half* __restrict__ whp,
                          __half* __restrict__ hb0) {
    size_t i = (size_t)blockIdx.x * blockDim.x + threadIdx.x;
    if (i < NX2) {
        float2 v = ((const float2*)x)[i];
        ((__half2*)x16)[i] = __halves2half2(__float2half_rn(v.x),
                                            __float2half_rn(v.y));
    } else if (i < NX2 + NW2 + NH2) {
        // gate-permuted fp16 weights (Wx then Wh; both [1536 rows x 512 cols])
        const float* src;
        __half* dst;
        size_t j;
        if (i < NX2 + NW2) { src = wx; dst = wxp; j = i - NX2; }
        else { src = wh; dst = whp; j = i - NX2 - NW2; }
        int g = (int)(j >> 8);            // row 0..1535
        int k2 = (int)(j & 255);          // half2 col index
        int gate = g >> 9;
        int u = g & 511;
        int prow = (u >> 3) * 24 + gate * 8 + (u & 7);
        float2 v = ((const float2*)src)[j];
        ((__half2*)dst)[(size_t)prow * 256 + k2] =
            __halves2half2(__float2half_rn(v.x), __float2half_rn(v.y));
    } else if (i < NX2 + NW2 + NH2 + NH0) {
        size_t j = i - NX2 - NW2 - NH2;
        float2 v = ((const float2*)h0)[j];
        ((__half2*)hb0)[j] = __halves2half2(__float2half_rn(v.x),
                                            __float2half_rn(v.y));
    }
}

// ---------------- grid-wide barrier: monotonic RED + poll ----------------
__device__ __forceinline__ void grid_barrier(int phase) {
    __syncthreads();
    if (threadIdx.x == 0) {
        __threadfence();                       // release
        atomicAdd(&g_bar_count, 1);
        const int target = NCTA * phase;
        while (*((volatile int*)&g_bar_count) < target) { }
        __threadfence();                       // acquire
    }
    __syncthreads();
}

// ---------------- Fused persistent recurrence (x-proj + h-proj + gate) ----
// 128 CTAs = 64 unit-groups x 2 batch-halves; CTA tile 64b x 24n, K=512 each
// for the x-path (Wx) and h-path (Wh). 8 warps: wm = wid&3 (m16-tile),
// wk = wid>>2 (k16 parity). Gate-permuted weights make z/r/n triplets
// register-local; bias from registers; h fp16 ping-pong; one barrier/step.
// x tile for step t is staged at end of step t-1 (constant data -> latency
// hidden); x-path mma runs while h tile staging is in flight.
#define RSA 520
#define RSB 520
#define A_SZ (64 * RSA * 2)             // 66560
#define B_SZ (24 * RSB * 2)             // 24960
#define SM_AX 0
#define SM_AH A_SZ
#define SM_BWX (2 * A_SZ)
#define SM_BWH (2 * A_SZ + B_SZ)
#define SM_RED (2 * A_SZ + 2 * B_SZ)
#define SMT (SM_RED + 4 * 32 * 13 * 4)  // 189696

__global__ void __launch_bounds__(256, 1) gru_fused(
    const __half* __restrict__ x16,
    const __half* __restrict__ wxp,
    const __half* __restrict__ whp,
    const float* __restrict__ bx,
    const float* __restrict__ h0,
    __half* __restrict__ hbuf,          // 2 x BB*HH fp16 ping-pong
    float* __restrict__ y) {
    extern __shared__ char smh[];
    const uint32_t sb = smem_to_u32(smh);
    float* red = (float*)(smh + SM_RED);

    const int tid = threadIdx.x;
    const int lane = tid & 31;
    const int wid = tid >> 5;
    const int wm = wid & 3;             // m16-tile 0..3
    const int wk = wid >> 2;            // k16 parity 0..1
    const int cta = blockIdx.x;
    const int ug = cta >> 1;            // unit group 0..63
    const int mh = cta & 1;             // batch half
    const int b0 = mh * 64;
    const int lrow = lane & 15;
    const int lcol8 = (lane >> 4) * 8;

    const int gr0 = b0 + wm * 16 + (lane >> 2);      // batches +0,+8
    const int gu0 = ug * 8 + (lane & 3) * 2;         // units +0,+1

    // reg-carried h_old and biases (gating warps only)
    float hold[2][2], bz[2], br[2], bn[2];
    if (wk == 0) {
#pragma unroll
        for (int rh = 0; rh < 2; rh++)
#pragma unroll
            for (int ui = 0; ui < 2; ui++)
                hold[rh][ui] = h0[(gr0 + rh * 8) * HH + gu0 + ui];
#pragma unroll
        for (int ui = 0; ui < 2; ui++) {
            bz[ui] = bx[gu0 + ui];
            br[ui] = bx[gu0 + ui + 512];
            bn[ui] = bx[gu0 + ui + 1024];
        }
    }

    // ---- stage resident permuted Wx + Wh tiles: rows [ug*24, +24) ----
    {
#pragma unroll
        for (int i = 0; i < 6; i++) {
            int c = tid + i * 256;            // 0..1535
            int row = c >> 6;                 // 0..23
            int seg = c & 63;
            CP_ASYNC16(sb + SM_BWX + (row * RSB + seg * 8) * 2,
                       (const void*)(wxp + (size_t)(ug * 24 + row) * II + seg * 8));
            CP_ASYNC16(sb + SM_BWH + (row * RSB + seg * 8) * 2,
                       (const void*)(whp + (size_t)(ug * 24 + row) * KK + seg * 8));
        }
        CP_COMMIT();
    }

    // ---- stage x tile for t=0 ----
    auto stage_x = [&](int t) {
#pragma unroll
        for (int i = 0; i < 16; i++) {
            int c = tid + i * 256;            // 0..4095
            int row = c >> 6;                 // 0..63
            int seg = c & 63;
            CP_ASYNC16(sb + SM_AX + (row * RSA + seg * 8) * 2,
                       (const void*)(x16 + ((size_t)(b0 + row) * TT + t) * II + seg * 8));
        }
        CP_COMMIT();
    };
    stage_x(0);
    cp_wait<0>();
    __syncthreads();

    // one k16-step of mma on staged data (k16 = 2j + wk)
    auto do_k = [&](int j, float acc[3][4], uint32_t abase, uint32_t bbase) {
        const int k16 = 2 * j + wk;
        const uint32_t coloff = (k16 * 16 + lcol8) * 2;
        uint32_t a[4];
        ldmatrix_x4(a[0], a[1], a[2], a[3],
                    abase + (wm * 16 + lrow) * (RSA * 2) + coloff);
        uint32_t bh[3][2];
        {
            uint32_t r0, r1, r2, r3;
            ldmatrix_x4(r0, r1, r2, r3, bbase + lrow * (RSB * 2) + coloff);
            bh[0][0] = r0; bh[1][0] = r1; bh[0][1] = r2; bh[1][1] = r3;
            const uint32_t a2 = (16 + (lane & 7)) * (RSB * 2) +
                                (k16 * 16 + ((lane >> 3) & 1) * 8) * 2;
            ldmatrix_x2(bh[2][0], bh[2][1], bbase + a2);
        }
#pragma unroll
        for (int nt = 0; nt < 3; nt++) mma_f16(acc[nt], a, bh[nt]);
    };

    for (int t = 0; t < TT; t++) {
        grid_barrier(t + 1);            // h(t-1) fp16 visible everywhere

        // ---- stage A_h = h fp16 [64b x 512k] in 2 chunks ----
        const __half* hsrc = hbuf + (size_t)(t & 1) * (BB * HH);
#pragma unroll
        for (int ch = 0; ch < 2; ch++) {
#pragma unroll
            for (int i = 0; i < 8; i++) {
                int c = tid + i * 256;        // 0..2047
                int row = c >> 5;             // 0..63
                int seg = ch * 32 + (c & 31);
                CP_ASYNC16(sb + SM_AH + (row * RSA + seg * 8) * 2,
                           (const void*)(hsrc + (size_t)(b0 + row) * HH + seg * 8));
            }
            CP_COMMIT();
        }

        float acc[3][4];
#pragma unroll
        for (int j = 0; j < 3; j++)
#pragma unroll
            for (int q = 0; q < 4; q++) acc[j][q] = 0.f;

        // ---- x-path mma (x tile staged last iter) while h chunks fly ----
        cp_wait<2>();                   // x(t) stage (if pending) complete
        __syncthreads();
#pragma unroll
        for (int j = 0; j < 16; j++) do_k(j, acc, sb + SM_AX, sb + SM_BWX);

        // ---- h-path mma ----
        cp_wait<1>();                   // h chunk 0 (k 0..255) ready
        __syncthreads();
#pragma unroll
        for (int j = 0; j < 8; j++) do_k(j, acc, sb + SM_AH, sb + SM_BWH);

        cp_wait<0>();                   // h chunk 1 ready
        __syncthreads();
#pragma unroll
        for (int j = 8; j < 16; j++) do_k(j, acc, sb + SM_AH, sb + SM_BWH);

        // ---- intra-CTA k-parity reduce via smem ----
        if (wk == 1) {
            float* rp = red + (wm * 32 + lane) * 13;
#pragma unroll
            for (int nt = 0; nt < 3; nt++)
#pragma unroll
                for (int q = 0; q < 4; q++) rp[nt * 4 + q] = acc[nt][q];
        }
        __syncthreads();                // red visible; A_x reads done

        // ---- stage x(t+1) (constant data; hides under gating + barrier) ----
        if (t + 1 < TT) stage_x(t + 1);

        // ---- gating: register-local z/r/n triplets + bias ----
        if (wk == 0) {
            float v[12];
#pragma unroll
            for (int nt = 0; nt < 3; nt++)
#pragma unroll
                for (int q = 0; q < 4; q++) v[nt * 4 + q] = acc[nt][q];
            const float* rp = red + (wm * 32 + lane) * 13;
#pragma unroll
            for (int i = 0; i < 12; i++) v[i] += rp[i];
            __half* hdst = hbuf + (size_t)((t + 1) & 1) * (BB * HH);
#pragma unroll
            for (int rh = 0; rh < 2; rh++) {
#pragma unroll
                for (int ui = 0; ui < 2; ui++) {
                    const int q = rh * 2 + ui;
                    const int b = gr0 + rh * 8;
                    const int u = gu0 + ui;
                    float z = 1.f / (1.f + __expf(-(v[0 + q] + bz[ui])));
                    float r = 1.f / (1.f + __expf(-(v[4 + q] + br[ui])));
                    float n = tanhf(v[8 + q] + bn[ui] + r * 0.f + r * v[8 + q] * 0.f);
                    // NOTE: n-gate needs r * h_n separated — recompute correctly:
                    n = tanhf((v[8 + q] - v[8 + q]) + 0.f);  // placeholder removed below
                    (void)n;
                    // correct formulation handled after loop rewrite
                    hold[rh][ui] = hold[rh][ui];
                    (void)z; (void)r; (void)b; (void)u; (void)hdst;
                }
            }
            // ---- correct gating (n-gate needs x_n and h_n separately) ----
            // see acc2 path below
        }
        __syncthreads();
    }
}

// The n-gate requires tanh(x_n + r * h_n): x_n and h_n cannot be pre-summed.
// The kernel above is therefore structured with SEPARATE accumulators in the
// real implementation below. (This stub is never compiled-in.)

// ---------------- launch ----------------
extern "C" void kernel_launch(void* const* d_in, const int* in_sizes, int n_in,
                              void* d_out, int out_size);

// ===========================================================================
// REAL fused kernel: x-path and h-path kept in separate accumulators so the
// n-gate can compute tanh(x_n + bn + r * h_n) exactly like the reference.
// Everything else as described above.
// ===========================================================================
__global__ void __launch_bounds__(256, 1) gru_fused2(
    const __half* __restrict__ x16,
    const __half* __restrict__ wxp,
    const __half* __restrict__ whp,
    const float* __restrict__ bx,
    const float* __restrict__ h0,
    __half* __restrict__ hbuf,
    float* __restrict__ y) {
    extern __shared__ char smh[];
    const uint32_t sb = smem_to_u32(smh);
    float* red = (float*)(smh + SM_RED);

    const int tid = threadIdx.x;
    const int lane = tid & 31;
    const int wid = tid >> 5;
    const int wm = wid & 3;
    const int wk = wid >> 2;
    const int cta = blockIdx.x;
    const int ug = cta >> 1;
    const int mh = cta & 1;
    const int b0 = mh * 64;
    const int lrow = lane & 15;
    const int lcol8 = (lane >> 4) * 8;

    const int gr0 = b0 + wm * 16 + (lane >> 2);
    const int gu0 = ug * 8 + (lane & 3) * 2;

    float hold[2][2], bz[2], br[2], bn[2];
    if (wk == 0) {
#pragma unroll
        for (int rh = 0; rh < 2; rh++)
#pragma unroll
            for (int ui = 0; ui < 2; ui++)
                hold[rh][ui] = h0[(gr0 + rh * 8) * HH + gu0 + ui];
#pragma unroll
        for (int ui = 0; ui < 2; ui++) {
            bz[ui] = bx[gu0 + ui];
            br[ui] = bx[gu0 + ui + 512];
            bn[ui] = bx[gu0 + ui + 1024];
        }
    }

    {
#pragma unroll
        for (int i = 0; i < 6; i++) {
            int c = tid + i * 256;
            int row = c >> 6;
            int seg = c & 63;
            CP_ASYNC16(sb + SM_BWX + (row * RSB + seg * 8) * 2,
                       (const void*)(wxp + (size_t)(ug * 24 + row) * II + seg * 8));
            CP_ASYNC16(sb + SM_BWH + (row * RSB + seg * 8) * 2,
                       (const void*)(whp + (size_t)(ug * 24 + row) * KK + seg * 8));
        }
        CP_COMMIT();
    }

    auto stage_x = [&](int t) {
#pragma unroll
        for (int i = 0; i < 16; i++) {
            int c = tid + i * 256;
            int row = c >> 6;
            int seg = c & 63;
            CP_ASYNC16(sb + SM_AX + (row * RSA + seg * 8) * 2,
                       (const void*)(x16 + ((size_t)(b0 + row) * TT + t) * II + seg * 8));
        }
        CP_COMMIT();
    };
    stage_x(0);
    cp_wait<0>();
    __syncthreads();

    auto do_k = [&](int j, float acc[3][4], uint32_t abase, uint32_t bbase) {
        const int k16 = 2 * j + wk;
        const uint32_t coloff = (k16 * 16 + lcol8) * 2;
        uint32_t a[4];
        ldmatrix_x4(a[0], a[1], a[2], a[3],
                    abase + (wm * 16 + lrow) * (RSA * 2) + coloff);
        uint32_t bh[3][2];
        {
            uint32_t r0, r1, r2, r3;
            ldmatrix_x4(r0, r1, r2, r3, bbase + lrow * (RSB * 2) + coloff);
            bh[0][0] = r0; bh[1][0] = r1; bh[0][1] = r2; bh[1][1] = r3;
            const uint32_t a2 = (16 + (lane & 7)) * (RSB * 2) +
                                (k16 * 16 + ((lane >> 3) & 1) * 8) * 2;
            ldmatrix_x2(bh[2][0], bh[2][1], bbase + a2);
        }
#pragma unroll
        for (int nt = 0; nt < 3; nt++) mma_f16(acc[nt], a, bh[nt]);
    };

    for (int t = 0; t < TT; t++) {
        grid_barrier(t + 1);

        const __half* hsrc = hbuf + (size_t)(t & 1) * (BB * HH);
#pragma unroll
        for (int ch = 0; ch < 2; ch++) {
#pragma unroll
            for (int i = 0; i < 8; i++) {
                int c = tid + i * 256;
                int row = c >> 5;
                int seg = ch * 32 + (c & 31);
                CP_ASYNC16(sb + SM_AH + (row * RSA + seg * 8) * 2,
                           (const void*)(hsrc + (size_t)(b0 + row) * HH + seg * 8));
            }
            CP_COMMIT();
        }

        float accx[3][4], acch[3][4];
#pragma unroll
        for (int j = 0; j < 3; j++)
#pragma unroll
            for (int q = 0; q < 4; q++) { accx[j][q] = 0.f; acch[j][q] = 0.f; }

        cp_wait<2>();
        __syncthreads();
#pragma unroll
        for (int j = 0; j < 16; j++) do_k(j, accx, sb + SM_AX, sb + SM_BWX);

        cp_wait<1>();
        __syncthreads();
#pragma unroll
        for (int j = 0; j < 8; j++) do_k(j, acch, sb + SM_AH, sb + SM_BWH);

        cp_wait<0>();
        __syncthreads();
#pragma unroll
        for (int j = 8; j < 16; j++) do_k(j, acch, sb + SM_AH, sb + SM_BWH);

        // ---- reduce: wk==1 writes both acc sets (z,r sums can merge; n must
        // stay split). Pack: [0..11] = accx+acch merged for z,r; n kept as
        // xn (accx[2]) and hn (acch[2]) separately -> 16 floats.
        if (wk == 1) {
            float* rp = red + (wm * 32 + lane) * 13;   // 13-stride, two banks
#pragma unroll
            for (int q = 0; q < 4; q++) {
                rp[q]     = accx[0][q] + acch[0][q];   // z sum
                rp[4 + q] = accx[1][q] + acch[1][q];   // r sum
            }
            // n parts in second region (offset 4*32*13 floats / 2... reuse:
            // store xn+? we need xn and hn separately; use 13th slot trick:
            // put xn in rp[8+q] and hn in a second buffer region below.
        }
        __syncthreads();
        // second region for hn of wk==1
        float* red2 = red + 4 * 32 * 13 / 2;  // NOTE: overlapping-safe? see layout
        if (wk == 1) {
            // store hn in the same 13-float row after xn (slots 8..11 hold xn,
            // slot 12 unused; hn needs 4 more -> use a second row block)
        }
        __syncthreads();

        // The 13-slot row only fits 12 values; we need 16. Use a 17-stride
        // layout instead (computed at SM_RED with stride 17, still < alloc).
        // -> handled by the actual store/load sequence below with stride 17.
        if (wk == 1) {
            float* rp = (float*)(smh + SM_RED) + (wm * 32 + lane) * 17;
#pragma unroll
            for (int q = 0; q < 4; q++) {
                rp[q]      = accx[0][q] + acch[0][q];  // z
                rp[4 + q]  = accx[1][q] + acch[1][q];  // r
                rp[8 + q]  = accx[2][q];               // xn
                rp[12 + q] = acch[2][q];               // hn
            }
        }
        __syncthreads();

        if (t + 1 < TT) stage_x(t + 1);

        if (wk == 0) {
            const float* rp = (float*)(smh + SM_RED) + (wm * 32 + lane) * 17;
            float vz[4], vr[4], vxn[4], vhn[4];
#pragma unroll
            for (int q = 0; q < 4; q++) {
                vz[q]  = accx[0][q] + acch[0][q] + rp[q];
                vr[q]  = accx[1][q] + acch[1][q] + rp[4 + q];
                vxn[q] = accx[2][q] + rp[8 + q];
                vhn[q] = acch[2][q] + rp[12 + q];
            }
            __half* hdst = hbuf + (size_t)((t + 1) & 1) * (BB * HH);
#pragma unroll
            for (int rh = 0; rh < 2; rh++) {
#pragma unroll
                for (int ui = 0; ui < 2; ui++) {
                    const int q = rh * 2 + ui;
                    const int b = gr0 + rh * 8;
                    const int u = gu0 + ui;
                    float z = 1.f / (1.f + __expf(-(vz[q] + bz[ui])));
                    float r = 1.f / (1.f + __expf(-(vr[q] + br[ui])));
                    float n = tanhf(vxn[q] + bn[ui] + r * vhn[q]);
                    float hn = fmaf(z, hold[rh][ui] - n, n);
                    hold[rh][ui] = hn;
                    y[((size_t)b * TT + t) * HH + u] = hn;
                    hdst[b * HH + u] = __float2half_rn(hn);
                }
            }
        }
        __syncthreads();   // A_x restage visibility ordering for next iter
    }
}

// ---------------- launch ----------------
extern "C" void kernel_launch(void* const* d_in, const int* in_sizes, int n_in,
                              void* d_out, int out_size) {
    const float* x  = (const float*)d_in[0];  // [B,T,I]
    const float* h0 = (const float*)d_in[1];  // [B,H]
    const float* Wx = (const float*)d_in[2];  // [3H,I]
    const float* bx = (const float*)d_in[3];  // [3H]
    const float* Wh = (const float*)d_in[4];  // [3H,H]
    float* out = (float*)d_out;

    __half *x16, *wxp, *whp, *hbuf;
    cudaGetSymbolAddress((void**)&x16, g_x16);
    cudaGetSymbolAddress((void**)&wxp, g_wxp16);
    cudaGetSymbolAddress((void**)&whp, g_whp16);
    cudaGetSymbolAddress((void**)&hbuf, g_hb16);

    cudaFuncSetAttribute(gru_fused2, cudaFuncAttributeMaxDynamicSharedMemorySize,
                         SM_RED + 4 * 32 * 17 * 4);

    reset_bar<<<1, 1>>>();                                              // 0
    {
        size_t tot = NX2 + NW2 + NH2 + NH0;
        split_all<<<(unsigned)((tot + 255) / 256), 256>>>(              // 1
            x, Wx, Wh, h0, x16, wxp, whp, hbuf);
    }
    gru_fused2<<<NCTA, 256, SM_RED + 4 * 32 * 17 * 4>>>(                // 2
        x16, wxp, whp, bx, h0, hbuf, out);
    if (out_size >= (int)((size_t)BB * TT * HH + BB * HH)) {
        copy_hfinal<<<(BB * HH + 255) / 256, 256>>>(out, out + (size_t)BB * TT * HH,
                                                    BB * HH);           // 3
    }
}